// round 1
// baseline (speedup 1.0000x reference)
#include <cuda_runtime.h>
#include <math.h>

// Problem constants
#define S_LEN 2048
#define H_DIM 4096
#define NQH   32
#define NKVH  8
#define HDIM  128
#define I_DIM 14336
#define QKV_N 6144          // (32 + 2*8) * 128
#define GU_N  28672         // 2 * I_DIM

// ---------------- scratch (device globals; allocation-free per harness rules) -------------
__device__ float g_xn[(size_t)S_LEN * H_DIM];        // rmsnorm1 output
__device__ float g_qkv[(size_t)S_LEN * QKV_N];       // qkv projections (rope applied in place)
__device__ float g_attn[(size_t)S_LEN * H_DIM];      // attention output (pre o-proj)
__device__ float g_x2[(size_t)S_LEN * H_DIM];        // rmsnorm2 output
__device__ float g_gu[(size_t)S_LEN * GU_N];         // gate_up output
__device__ float g_h[(size_t)S_LEN * I_DIM];         // silu(gate)*up

// ---------------- RMSNorm: one block per row ----------------
__global__ __launch_bounds__(256) void rmsnorm_kernel(const float* __restrict__ x,
                                                      const float* __restrict__ w,
                                                      float* __restrict__ out) {
    int row = blockIdx.x;
    int tid = threadIdx.x;
    const float4* xr = (const float4*)(x + (size_t)row * H_DIM);
    float ss = 0.f;
#pragma unroll
    for (int it = 0; it < 4; it++) {
        float4 t = xr[tid + it * 256];
        ss += t.x * t.x + t.y * t.y + t.z * t.z + t.w * t.w;
    }
#pragma unroll
    for (int m = 16; m; m >>= 1) ss += __shfl_xor_sync(0xffffffffu, ss, m);
    __shared__ float warps[8];
    if ((tid & 31) == 0) warps[tid >> 5] = ss;
    __syncthreads();
    if (tid < 8) {
        float s2 = warps[tid];
#pragma unroll
        for (int m = 4; m; m >>= 1) s2 += __shfl_xor_sync(0xffu, s2, m);
        if (tid == 0) warps[0] = s2;
    }
    __syncthreads();
    float inv = rsqrtf(warps[0] * (1.0f / H_DIM) + 1e-5f);
    const float4* w4 = (const float4*)w;
    float4* o4 = (float4*)(out + (size_t)row * H_DIM);
#pragma unroll
    for (int it = 0; it < 4; it++) {
        int i = tid + it * 256;
        float4 t = xr[i], ww = w4[i];
        float4 r;
        r.x = t.x * inv * ww.x;
        r.y = t.y * inv * ww.y;
        r.z = t.z * inv * ww.z;
        r.w = t.w * inv * ww.w;
        o4[i] = r;
    }
}

// ---------------- SGEMM: 128x128 tile, K-tile 8, 256 threads, 8x8 per-thread ----------------
// A[M,K] row-major, B[K,N] row-major, C[M,N]. M%128==0, N%128==0, K%8==0 (all true here).
template <bool ADD_RES>
__global__ __launch_bounds__(256) void sgemm_kernel(const float* __restrict__ A,
                                                    const float* __restrict__ B,
                                                    const float* __restrict__ Res,
                                                    float* __restrict__ C,
                                                    int M, int N, int K) {
    __shared__ float As[8][128];
    __shared__ float Bs[8][128];
    int bx = blockIdx.x, by = blockIdx.y;
    int tid = threadIdx.x;
    int tx = tid & 15, ty = tid >> 4;

    const float* Ab = A + (size_t)(by * 128) * K;
    const float* Bb = B + (size_t)(bx * 128);

    int a_row = tid >> 1;          // 0..127
    int a_col = (tid & 1) * 4;     // 0 or 4
    int b_row = tid >> 5;          // 0..7
    int b_col = (tid & 31) * 4;    // 0..124

    float c[8][8];
#pragma unroll
    for (int i = 0; i < 8; i++)
#pragma unroll
        for (int j = 0; j < 8; j++) c[i][j] = 0.f;

    for (int k0 = 0; k0 < K; k0 += 8) {
        float4 av = *(const float4*)(Ab + (size_t)a_row * K + k0 + a_col);
        float4 bv = *(const float4*)(Bb + (size_t)(k0 + b_row) * N + b_col);
        __syncthreads();
        As[a_col + 0][a_row] = av.x;
        As[a_col + 1][a_row] = av.y;
        As[a_col + 2][a_row] = av.z;
        As[a_col + 3][a_row] = av.w;
        *(float4*)&Bs[b_row][b_col] = bv;
        __syncthreads();
#pragma unroll
        for (int kk = 0; kk < 8; kk++) {
            float a[8], b[8];
            *(float4*)(a)     = *(const float4*)&As[kk][ty * 4];
            *(float4*)(a + 4) = *(const float4*)&As[kk][64 + ty * 4];
            *(float4*)(b)     = *(const float4*)&Bs[kk][tx * 4];
            *(float4*)(b + 4) = *(const float4*)&Bs[kk][64 + tx * 4];
#pragma unroll
            for (int i = 0; i < 8; i++)
#pragma unroll
                for (int j = 0; j < 8; j++) c[i][j] += a[i] * b[j];
        }
    }

    // Epilogue: two float4 stores per row-fragment
#pragma unroll
    for (int i = 0; i < 8; i++) {
        int mi = by * 128 + ((i < 4) ? (ty * 4 + i) : (64 + ty * 4 + i - 4));
        size_t base = (size_t)mi * N + bx * 128;
        float4 v0 = make_float4(c[i][0], c[i][1], c[i][2], c[i][3]);
        float4 v1 = make_float4(c[i][4], c[i][5], c[i][6], c[i][7]);
        if (ADD_RES) {
            float4 r0 = *(const float4*)(Res + base + tx * 4);
            float4 r1 = *(const float4*)(Res + base + 64 + tx * 4);
            v0.x += r0.x; v0.y += r0.y; v0.z += r0.z; v0.w += r0.w;
            v1.x += r1.x; v1.y += r1.y; v1.z += r1.z; v1.w += r1.w;
        }
        *(float4*)(C + base + tx * 4) = v0;
        *(float4*)(C + base + 64 + tx * 4) = v1;
    }
}

// ---------------- RoPE in-place on q (heads 0..31) and k (heads 32..39) ----------------
__global__ void rope_kernel(float* __restrict__ qkv) {
    int s = blockIdx.x;          // position == sequence index (positions = arange)
    int h = blockIdx.y;          // 0..39 : q heads then k heads (contiguous layout)
    int d = threadIdx.x;         // 0..63
    float* base = qkv + (size_t)s * QKV_N + h * HDIM;
    float inv = 1.0f / powf(10000.0f, (float)d * (1.0f / 64.0f));
    float ang = (float)s * inv;
    float sn, cs;
    sincosf(ang, &sn, &cs);
    float x1 = base[d], x2 = base[d + 64];
    base[d]      = x1 * cs - x2 * sn;
    base[d + 64] = x2 * cs + x1 * sn;
}

// ---------------- Flash attention (causal GQA), fp32 ----------------
// Block: 64 queries of one head. 256 threads = 16x16. S-tile 64x64, online softmax.
#define BM 64
#define BN 64
#define LDQ 132   // padded row stride for Q/K/V tiles
#define LDP 68    // padded row stride for P tile
#define ATTN_SMEM ((3 * BM * LDQ + BM * LDP) * 4)

__global__ __launch_bounds__(256) void attn_kernel(const float* __restrict__ qkv,
                                                   float* __restrict__ out) {
    extern __shared__ float sm[];
    float* Qs = sm;                   // BM x LDQ
    float* Ks = Qs + BM * LDQ;        // BM x LDQ
    float* Vs = Ks + BM * LDQ;        // BM x LDQ
    float* Ps = Vs + BM * LDQ;        // BM x LDP

    int qb = blockIdx.x;
    int h = blockIdx.y;
    int kvh = h >> 2;                 // G = 4
    int tid = threadIdx.x;
    int tx = tid & 15, ty = tid >> 4;

    // load Q tile
    for (int i = tid; i < BM * (HDIM / 4); i += 256) {
        int r = i >> 5, c = (i & 31) << 2;
        *(float4*)&Qs[r * LDQ + c] =
            *(const float4*)&qkv[(size_t)(qb * BM + r) * QKV_N + h * HDIM + c];
    }

    float m_i[4], l_i[4], acc[4][8];
#pragma unroll
    for (int i = 0; i < 4; i++) {
        m_i[i] = -INFINITY;
        l_i[i] = 0.f;
#pragma unroll
        for (int j = 0; j < 8; j++) acc[i][j] = 0.f;
    }
    const float scale = 0.08838834764831845f;  // 1/sqrt(128)

    for (int kb = 0; kb <= qb; ++kb) {
        __syncthreads();
        for (int i = tid; i < BM * (HDIM / 4); i += 256) {
            int r = i >> 5, c = (i & 31) << 2;
            size_t srow = (size_t)(kb * BM + r) * QKV_N;
            *(float4*)&Ks[r * LDQ + c] =
                *(const float4*)&qkv[srow + NQH * HDIM + kvh * HDIM + c];
            *(float4*)&Vs[r * LDQ + c] =
                *(const float4*)&qkv[srow + (NQH + NKVH) * HDIM + kvh * HDIM + c];
        }
        __syncthreads();

        // S = Q K^T (4x4 per thread)
        float sv[4][4];
#pragma unroll
        for (int i = 0; i < 4; i++)
#pragma unroll
            for (int j = 0; j < 4; j++) sv[i][j] = 0.f;

        for (int d = 0; d < HDIM; d += 4) {
            float4 a4[4], b4[4];
#pragma unroll
            for (int i = 0; i < 4; i++) a4[i] = *(const float4*)&Qs[(ty * 4 + i) * LDQ + d];
#pragma unroll
            for (int j = 0; j < 4; j++) b4[j] = *(const float4*)&Ks[(tx * 4 + j) * LDQ + d];
#pragma unroll
            for (int i = 0; i < 4; i++)
#pragma unroll
                for (int j = 0; j < 4; j++)
                    sv[i][j] += a4[i].x * b4[j].x + a4[i].y * b4[j].y +
                                a4[i].z * b4[j].z + a4[i].w * b4[j].w;
        }
#pragma unroll
        for (int i = 0; i < 4; i++)
#pragma unroll
            for (int j = 0; j < 4; j++) sv[i][j] *= scale;

        if (kb == qb) {
#pragma unroll
            for (int i = 0; i < 4; i++)
#pragma unroll
                for (int j = 0; j < 4; j++)
                    if (tx * 4 + j > ty * 4 + i) sv[i][j] = -INFINITY;
        }

        // online softmax (row groups of 16 lanes)
#pragma unroll
        for (int i = 0; i < 4; i++) {
            float rm = fmaxf(fmaxf(sv[i][0], sv[i][1]), fmaxf(sv[i][2], sv[i][3]));
#pragma unroll
            for (int m = 1; m < 16; m <<= 1) rm = fmaxf(rm, __shfl_xor_sync(0xffffffffu, rm, m));
            float mnew = fmaxf(m_i[i], rm);
            float rs = 0.f;
#pragma unroll
            for (int j = 0; j < 4; j++) {
                sv[i][j] = __expf(sv[i][j] - mnew);
                rs += sv[i][j];
            }
#pragma unroll
            for (int m = 1; m < 16; m <<= 1) rs += __shfl_xor_sync(0xffffffffu, rs, m);
            float alpha = __expf(m_i[i] - mnew);
            l_i[i] = l_i[i] * alpha + rs;
            m_i[i] = mnew;
#pragma unroll
            for (int j = 0; j < 8; j++) acc[i][j] *= alpha;
            *(float4*)&Ps[(ty * 4 + i) * LDP + tx * 4] =
                make_float4(sv[i][0], sv[i][1], sv[i][2], sv[i][3]);
        }
        __syncthreads();

        // O += P @ V ; thread owns rows ty*4..+3, cols tx*8..+7
        for (int k = 0; k < BN; k += 4) {
            float4 p4[4];
#pragma unroll
            for (int i = 0; i < 4; i++) p4[i] = *(const float4*)&Ps[(ty * 4 + i) * LDP + k];
#pragma unroll
            for (int kk = 0; kk < 4; kk++) {
                float4 v0 = *(const float4*)&Vs[(k + kk) * LDQ + tx * 8];
                float4 v1 = *(const float4*)&Vs[(k + kk) * LDQ + tx * 8 + 4];
#pragma unroll
                for (int i = 0; i < 4; i++) {
                    float p = ((const float*)&p4[i])[kk];
                    acc[i][0] += p * v0.x; acc[i][1] += p * v0.y;
                    acc[i][2] += p * v0.z; acc[i][3] += p * v0.w;
                    acc[i][4] += p * v1.x; acc[i][5] += p * v1.y;
                    acc[i][6] += p * v1.z; acc[i][7] += p * v1.w;
                }
            }
        }
    }

    // write normalized output
#pragma unroll
    for (int i = 0; i < 4; i++) {
        float invl = 1.0f / l_i[i];
        size_t base = (size_t)(qb * BM + ty * 4 + i) * H_DIM + h * HDIM + tx * 8;
        float4 o0 = make_float4(acc[i][0] * invl, acc[i][1] * invl, acc[i][2] * invl, acc[i][3] * invl);
        float4 o1 = make_float4(acc[i][4] * invl, acc[i][5] * invl, acc[i][6] * invl, acc[i][7] * invl);
        *(float4*)&out[base] = o0;
        *(float4*)&out[base + 4] = o1;
    }
}

// ---------------- SiLU(gate) * up ----------------
__global__ void silu_mul_kernel(const float* __restrict__ gu, float* __restrict__ h) {
    size_t idx = (size_t)blockIdx.x * blockDim.x + threadIdx.x;
    const size_t n4 = (size_t)S_LEN * I_DIM / 4;
    if (idx >= n4) return;
    int s = (int)(idx / (I_DIM / 4));
    int c = (int)(idx % (I_DIM / 4)) * 4;
    float4 g = *(const float4*)&gu[(size_t)s * GU_N + c];
    float4 u = *(const float4*)&gu[(size_t)s * GU_N + I_DIM + c];
    float4 r;
    r.x = g.x / (1.f + __expf(-g.x)) * u.x;
    r.y = g.y / (1.f + __expf(-g.y)) * u.y;
    r.z = g.z / (1.f + __expf(-g.z)) * u.z;
    r.w = g.w / (1.f + __expf(-g.w)) * u.w;
    *(float4*)&h[(size_t)s * I_DIM + c] = r;
}

// ---------------- host launcher ----------------
extern "C" void kernel_launch(void* const* d_in, const int* in_sizes, int n_in,
                              void* d_out, int out_size) {
    (void)in_sizes; (void)n_in; (void)out_size;
    // metadata order: positions, hidden_states, w_qkv, w_o, w_gate_up, w_down, ln1_w, ln2_w
    const float* hidden = (const float*)d_in[1];
    const float* w_qkv  = (const float*)d_in[2];
    const float* w_o    = (const float*)d_in[3];
    const float* w_gu   = (const float*)d_in[4];
    const float* w_down = (const float*)d_in[5];
    const float* ln1    = (const float*)d_in[6];
    const float* ln2    = (const float*)d_in[7];

    float* out = (float*)d_out;                            // (out, residual) concatenated
    float* residual = out + (size_t)S_LEN * H_DIM;

    float *xn, *qkv, *attnb, *x2, *gu, *hbuf;
    cudaGetSymbolAddress((void**)&xn, g_xn);
    cudaGetSymbolAddress((void**)&qkv, g_qkv);
    cudaGetSymbolAddress((void**)&attnb, g_attn);
    cudaGetSymbolAddress((void**)&x2, g_x2);
    cudaGetSymbolAddress((void**)&gu, g_gu);
    cudaGetSymbolAddress((void**)&hbuf, g_h);

    cudaFuncSetAttribute(attn_kernel, cudaFuncAttributeMaxDynamicSharedMemorySize, ATTN_SMEM);

    // 1) rmsnorm1
    rmsnorm_kernel<<<S_LEN, 256>>>(hidden, ln1, xn);
    // 2) qkv = xn @ w_qkv
    sgemm_kernel<false><<<dim3(QKV_N / 128, S_LEN / 128), 256>>>(xn, w_qkv, nullptr, qkv,
                                                                 S_LEN, QKV_N, H_DIM);
    // 3) rope on q,k in place
    rope_kernel<<<dim3(S_LEN, NQH + NKVH), 64>>>(qkv);
    // 4) causal GQA flash attention
    attn_kernel<<<dim3(S_LEN / BM, NQH), 256, ATTN_SMEM>>>(qkv, attnb);
    // 5) residual = attn @ w_o + hidden  (written into second half of d_out)
    sgemm_kernel<true><<<dim3(H_DIM / 128, S_LEN / 128), 256>>>(attnb, w_o, hidden, residual,
                                                                S_LEN, H_DIM, NQH * HDIM);
    // 6) rmsnorm2
    rmsnorm_kernel<<<S_LEN, 256>>>(residual, ln2, x2);
    // 7) gate_up = x2 @ w_gate_up
    sgemm_kernel<false><<<dim3(GU_N / 128, S_LEN / 128), 256>>>(x2, w_gu, nullptr, gu,
                                                                S_LEN, GU_N, H_DIM);
    // 8) h = silu(gate) * up
    {
        size_t n4 = (size_t)S_LEN * I_DIM / 4;
        int blocks = (int)((n4 + 255) / 256);
        silu_mul_kernel<<<blocks, 256>>>(gu, hbuf);
    }
    // 9) out = h @ w_down  (first half of d_out)
    sgemm_kernel<false><<<dim3(H_DIM / 128, S_LEN / 128), 256>>>(hbuf, w_down, nullptr, out,
                                                                 S_LEN, H_DIM, I_DIM);
}

// round 3
// speedup vs baseline: 1.9349x; 1.9349x over previous
#include <cuda_runtime.h>
#include <cuda_bf16.h>
#include <math.h>
#include <stdint.h>

// Problem constants
#define S_LEN 2048
#define H_DIM 4096
#define NQH   32
#define NKVH  8
#define HDIM  128
#define I_DIM 14336
#define QKV_N 6144
#define GU_N  28672

typedef __nv_bfloat16 bf16;

// ---------------- scratch (device globals) ----------------
__device__ float g_qkv[(size_t)S_LEN * QKV_N];
__device__ float g_gu [(size_t)S_LEN * GU_N];

__device__ bf16 g_xn_h [(size_t)S_LEN * H_DIM];
__device__ bf16 g_xn_l [(size_t)S_LEN * H_DIM];
__device__ bf16 g_at_h [(size_t)S_LEN * H_DIM];
__device__ bf16 g_at_l [(size_t)S_LEN * H_DIM];
__device__ bf16 g_x2_h [(size_t)S_LEN * H_DIM];
__device__ bf16 g_x2_l [(size_t)S_LEN * H_DIM];
__device__ bf16 g_h_h  [(size_t)S_LEN * I_DIM];
__device__ bf16 g_h_l  [(size_t)S_LEN * I_DIM];

// transposed+split weights: [N, K] bf16
__device__ bf16 g_wqkv_h[(size_t)QKV_N * H_DIM];
__device__ bf16 g_wqkv_l[(size_t)QKV_N * H_DIM];
__device__ bf16 g_wo_h  [(size_t)H_DIM * H_DIM];
__device__ bf16 g_wo_l  [(size_t)H_DIM * H_DIM];
__device__ bf16 g_wgu_h [(size_t)GU_N * H_DIM];
__device__ bf16 g_wgu_l [(size_t)GU_N * H_DIM];
__device__ bf16 g_wdn_h [(size_t)H_DIM * I_DIM];
__device__ bf16 g_wdn_l [(size_t)H_DIM * I_DIM];

// ---------------- device helpers ----------------
__device__ __forceinline__ uint32_t su32(const void* p) {
    uint32_t a;
    asm("{ .reg .u64 t; cvta.to.shared.u64 t, %1; cvt.u32.u64 %0, t; }" : "=r"(a) : "l"(p));
    return a;
}
__device__ __forceinline__ void cp16(uint32_t dst, const void* src) {
    asm volatile("cp.async.cg.shared.global [%0], [%1], 16;" :: "r"(dst), "l"(src) : "memory");
}
__device__ __forceinline__ void cp_commit() {
    asm volatile("cp.async.commit_group;" ::: "memory");
}
template <int N>
__device__ __forceinline__ void cp_wait() {
    asm volatile("cp.async.wait_group %0;" :: "n"(N) : "memory");
}
__device__ __forceinline__ void ldm_x4(uint32_t* r, uint32_t addr) {
    asm volatile("ldmatrix.sync.aligned.m8n8.x4.shared.b16 {%0,%1,%2,%3}, [%4];"
                 : "=r"(r[0]), "=r"(r[1]), "=r"(r[2]), "=r"(r[3]) : "r"(addr));
}
__device__ __forceinline__ void mma_bf16(float* c, const uint32_t* a, const uint32_t* b) {
    asm volatile(
        "mma.sync.aligned.m16n8k16.row.col.f32.bf16.bf16.f32 "
        "{%0,%1,%2,%3}, {%4,%5,%6,%7}, {%8,%9}, {%0,%1,%2,%3};"
        : "+f"(c[0]), "+f"(c[1]), "+f"(c[2]), "+f"(c[3])
        : "r"(a[0]), "r"(a[1]), "r"(a[2]), "r"(a[3]), "r"(b[0]), "r"(b[1]));
}
__device__ __forceinline__ void split_bf16(float x, bf16& h, bf16& l) {
    h = __float2bfloat16(x);
    l = __float2bfloat16(x - __bfloat162float(h));
}

// ---------------- split-bf16 GEMM via mma.sync ----------------
// C[M,N] = A[M,K] * B[N,K]^T with A=(Ah+Al), B=(Bh+Bl); 3 MMA terms.
// CTA tile 128x128, K-tile 32, 2-stage cp.async pipeline, 8 warps (2x4), warp tile 64x32.
#define KT 32
#define ROW_ELEMS 40                       // 32 data + 8 pad (80B row stride)
#define TILE_BYTES (128 * ROW_ELEMS * 2)   // 10240
#define STAGE_BYTES (4 * TILE_BYTES)       // 40960: Ah, Al, Bh, Bl
#define GEMM_SMEM (2 * STAGE_BYTES)        // 81920

template <bool ADD_RES>
__global__ __launch_bounds__(256) void mma_gemm(const bf16* __restrict__ Ah,
                                                const bf16* __restrict__ Al,
                                                const bf16* __restrict__ Bh,
                                                const bf16* __restrict__ Bl,
                                                const float* __restrict__ Res,
                                                float* __restrict__ C, int N, int K) {
    extern __shared__ char smem_raw[];
    uint32_t smem = su32(smem_raw);
    int tid = threadIdx.x;
    int lane = tid & 31, wid = tid >> 5;
    int bm = blockIdx.x, bn = blockIdx.y;

    // loader mapping: each thread does 8 cp.async of 16B per stage
    int rowt = tid >> 2;          // 0..63
    int kq = tid & 3;             // 16B chunk within 64B k-row
    const bf16* gptr[4][2];
    {
        const bf16* a0 = Ah + (size_t)(bm * 128 + rowt) * K + kq * 8;
        const bf16* a1 = Al + (size_t)(bm * 128 + rowt) * K + kq * 8;
        const bf16* b0 = Bh + (size_t)(bn * 128 + rowt) * K + kq * 8;
        const bf16* b1 = Bl + (size_t)(bn * 128 + rowt) * K + kq * 8;
        gptr[0][0] = a0;  gptr[0][1] = a0 + (size_t)64 * K;
        gptr[1][0] = a1;  gptr[1][1] = a1 + (size_t)64 * K;
        gptr[2][0] = b0;  gptr[2][1] = b0 + (size_t)64 * K;
        gptr[3][0] = b1;  gptr[3][1] = b1 + (size_t)64 * K;
    }
    uint32_t sdst[4][2];
#pragma unroll
    for (int t4 = 0; t4 < 4; t4++)
#pragma unroll
        for (int hf = 0; hf < 2; hf++)
            sdst[t4][hf] = smem + t4 * TILE_BYTES + (hf * 64 + rowt) * (ROW_ELEMS * 2) + kq * 16;

    // fragment lane offsets
    int laneAr = lane & 15;
    int laneAk = (lane >> 4) * 8;
    uint32_t offA = (laneAr * ROW_ELEMS + laneAk) * 2;
    int laneBr = ((lane >> 4) << 3) + (lane & 7);
    int laneBk = ((lane >> 3) & 1) * 8;
    uint32_t offB = (laneBr * ROW_ELEMS + laneBk) * 2;

    int mbase = (wid >> 2) * 64;   // 0 or 64
    int nbase = (wid & 3) * 32;    // 0..96

    float acc[4][4][4];
#pragma unroll
    for (int mt = 0; mt < 4; mt++)
#pragma unroll
        for (int nt = 0; nt < 4; nt++)
#pragma unroll
            for (int i = 0; i < 4; i++) acc[mt][nt][i] = 0.f;

    int T = K / KT;

    auto issue = [&](int t) {
        int s = t & 1;
        uint32_t sb = s * STAGE_BYTES;
        int ke = t * KT;
#pragma unroll
        for (int t4 = 0; t4 < 4; t4++)
#pragma unroll
            for (int hf = 0; hf < 2; hf++)
                cp16(sdst[t4][hf] + sb, gptr[t4][hf] + ke);
        cp_commit();
    };

    issue(0);
    issue(1);

    for (int t = 0; t < T; t++) {
        if (t + 2 < T) cp_wait<1>(); else cp_wait<0>();
        __syncthreads();

        uint32_t sb = smem + (t & 1) * STAGE_BYTES;
        uint32_t bAh = sb, bAl = sb + TILE_BYTES, bBh = sb + 2 * TILE_BYTES, bBl = sb + 3 * TILE_BYTES;
#pragma unroll
        for (int ks = 0; ks < 2; ks++) {
            uint32_t ah[4][4], al[4][4], bh[2][4], bl[2][4];
#pragma unroll
            for (int mt = 0; mt < 4; mt++) {
                uint32_t ro = (mbase + mt * 16) * (ROW_ELEMS * 2) + ks * 32;
                ldm_x4(ah[mt], bAh + ro + offA);
                ldm_x4(al[mt], bAl + ro + offA);
            }
#pragma unroll
            for (int np = 0; np < 2; np++) {
                uint32_t ro = (nbase + np * 16) * (ROW_ELEMS * 2) + ks * 32;
                ldm_x4(bh[np], bBh + ro + offB);
                ldm_x4(bl[np], bBl + ro + offB);
            }
#pragma unroll
            for (int mt = 0; mt < 4; mt++)
#pragma unroll
                for (int nt = 0; nt < 4; nt++) {
                    int np = nt >> 1, hh = nt & 1;
                    mma_bf16(acc[mt][nt], ah[mt], &bh[np][2 * hh]);
                    mma_bf16(acc[mt][nt], al[mt], &bh[np][2 * hh]);
                    mma_bf16(acc[mt][nt], ah[mt], &bl[np][2 * hh]);
                }
        }
        __syncthreads();
        if (t + 2 < T) issue(t + 2);
    }

    // epilogue
    int lr = lane >> 2, lc = (lane & 3) * 2;
#pragma unroll
    for (int mt = 0; mt < 4; mt++)
#pragma unroll
        for (int nt = 0; nt < 4; nt++) {
            int r0 = bm * 128 + mbase + mt * 16 + lr;
            int c = bn * 128 + nbase + nt * 8 + lc;
            float2 v0 = make_float2(acc[mt][nt][0], acc[mt][nt][1]);
            float2 v1 = make_float2(acc[mt][nt][2], acc[mt][nt][3]);
            size_t i0 = (size_t)r0 * N + c;
            size_t i1 = (size_t)(r0 + 8) * N + c;
            if (ADD_RES) {
                float2 q0 = *(const float2*)(Res + i0);
                float2 q1 = *(const float2*)(Res + i1);
                v0.x += q0.x; v0.y += q0.y;
                v1.x += q1.x; v1.y += q1.y;
            }
            *(float2*)(C + i0) = v0;
            *(float2*)(C + i1) = v1;
        }
}

// ---------------- weight transpose + hi/lo split: W[K,N] -> Wh/Wl[N,K] ----------------
__global__ __launch_bounds__(256) void wsplit_t_kernel(const float* __restrict__ W,
                                                       bf16* __restrict__ Wh, bf16* __restrict__ Wl,
                                                       int K, int N) {
    __shared__ float t[32][33];
    int n0 = blockIdx.x * 32, k0 = blockIdx.y * 32;
    int tx = threadIdx.x & 31, ty = threadIdx.x >> 5;
#pragma unroll
    for (int i = 0; i < 4; i++)
        t[ty + 8 * i][tx] = W[(size_t)(k0 + ty + 8 * i) * N + n0 + tx];
    __syncthreads();
#pragma unroll
    for (int i = 0; i < 4; i++) {
        float v = t[tx][ty + 8 * i];
        bf16 h, l;
        split_bf16(v, h, l);
        size_t o = (size_t)(n0 + ty + 8 * i) * K + k0 + tx;
        Wh[o] = h;
        Wl[o] = l;
    }
}

// ---------------- RMSNorm -> split bf16 ----------------
__global__ __launch_bounds__(256) void rmsnorm_split_kernel(const float* __restrict__ x,
                                                            const float* __restrict__ w,
                                                            bf16* __restrict__ oh,
                                                            bf16* __restrict__ ol) {
    int row = blockIdx.x;
    int tid = threadIdx.x;
    const float4* xr = (const float4*)(x + (size_t)row * H_DIM);
    float ss = 0.f;
#pragma unroll
    for (int it = 0; it < 4; it++) {
        float4 t = xr[tid + it * 256];
        ss += t.x * t.x + t.y * t.y + t.z * t.z + t.w * t.w;
    }
#pragma unroll
    for (int m = 16; m; m >>= 1) ss += __shfl_xor_sync(0xffffffffu, ss, m);
    __shared__ float warps[8];
    if ((tid & 31) == 0) warps[tid >> 5] = ss;
    __syncthreads();
    if (tid < 8) {
        float s2 = warps[tid];
#pragma unroll
        for (int m = 4; m; m >>= 1) s2 += __shfl_xor_sync(0xffu, s2, m);
        if (tid == 0) warps[0] = s2;
    }
    __syncthreads();
    float inv = rsqrtf(warps[0] * (1.0f / H_DIM) + 1e-5f);
    const float4* w4 = (const float4*)w;
#pragma unroll
    for (int it = 0; it < 4; it++) {
        int i = tid + it * 256;
        float4 t = xr[i], ww = w4[i];
        float v[4] = {t.x * inv * ww.x, t.y * inv * ww.y, t.z * inv * ww.z, t.w * inv * ww.w};
        size_t o = (size_t)row * H_DIM + 4 * i;
#pragma unroll
        for (int j = 0; j < 4; j++) {
            bf16 h, l;
            split_bf16(v[j], h, l);
            oh[o + j] = h;
            ol[o + j] = l;
        }
    }
}

// ---------------- RoPE in-place ----------------
__global__ void rope_kernel(float* __restrict__ qkv) {
    int s = blockIdx.x;
    int h = blockIdx.y;           // 0..39
    int d = threadIdx.x;          // 0..63
    float* base = qkv + (size_t)s * QKV_N + h * HDIM;
    float inv = 1.0f / powf(10000.0f, (float)d * (1.0f / 64.0f));
    float ang = (float)s * inv;
    float sn, cs;
    sincosf(ang, &sn, &cs);
    float x1 = base[d], x2 = base[d + 64];
    base[d]      = x1 * cs - x2 * sn;
    base[d + 64] = x2 * cs + x1 * sn;
}

// ---------------- Flash attention (causal GQA), fp32, split bf16 output ----------------
#define BM 64
#define BN 64
#define LDQ 132
#define LDP 68
#define ATTN_SMEM ((3 * BM * LDQ + BM * LDP) * 4)

__global__ __launch_bounds__(256) void attn_kernel(const float* __restrict__ qkv,
                                                   bf16* __restrict__ oh,
                                                   bf16* __restrict__ ol) {
    extern __shared__ float sm[];
    float* Qs = sm;
    float* Ks = Qs + BM * LDQ;
    float* Vs = Ks + BM * LDQ;
    float* Ps = Vs + BM * LDQ;

    int qb = blockIdx.x;
    int h = blockIdx.y;
    int kvh = h >> 2;
    int tid = threadIdx.x;
    int tx = tid & 15, ty = tid >> 4;

    for (int i = tid; i < BM * (HDIM / 4); i += 256) {
        int r = i >> 5, c = (i & 31) << 2;
        *(float4*)&Qs[r * LDQ + c] =
            *(const float4*)&qkv[(size_t)(qb * BM + r) * QKV_N + h * HDIM + c];
    }

    float m_i[4], l_i[4], acc[4][8];
#pragma unroll
    for (int i = 0; i < 4; i++) {
        m_i[i] = -INFINITY;
        l_i[i] = 0.f;
#pragma unroll
        for (int j = 0; j < 8; j++) acc[i][j] = 0.f;
    }
    const float scale = 0.08838834764831845f;

    for (int kb = 0; kb <= qb; ++kb) {
        __syncthreads();
        for (int i = tid; i < BM * (HDIM / 4); i += 256) {
            int r = i >> 5, c = (i & 31) << 2;
            size_t srow = (size_t)(kb * BM + r) * QKV_N;
            *(float4*)&Ks[r * LDQ + c] =
                *(const float4*)&qkv[srow + NQH * HDIM + kvh * HDIM + c];
            *(float4*)&Vs[r * LDQ + c] =
                *(const float4*)&qkv[srow + (NQH + NKVH) * HDIM + kvh * HDIM + c];
        }
        __syncthreads();

        float sv[4][4];
#pragma unroll
        for (int i = 0; i < 4; i++)
#pragma unroll
            for (int j = 0; j < 4; j++) sv[i][j] = 0.f;

        for (int d = 0; d < HDIM; d += 4) {
            float4 a4[4], b4[4];
#pragma unroll
            for (int i = 0; i < 4; i++) a4[i] = *(const float4*)&Qs[(ty * 4 + i) * LDQ + d];
#pragma unroll
            for (int j = 0; j < 4; j++) b4[j] = *(const float4*)&Ks[(tx * 4 + j) * LDQ + d];
#pragma unroll
            for (int i = 0; i < 4; i++)
#pragma unroll
                for (int j = 0; j < 4; j++)
                    sv[i][j] += a4[i].x * b4[j].x + a4[i].y * b4[j].y +
                                a4[i].z * b4[j].z + a4[i].w * b4[j].w;
        }
#pragma unroll
        for (int i = 0; i < 4; i++)
#pragma unroll
            for (int j = 0; j < 4; j++) sv[i][j] *= scale;

        if (kb == qb) {
#pragma unroll
            for (int i = 0; i < 4; i++)
#pragma unroll
                for (int j = 0; j < 4; j++)
                    if (tx * 4 + j > ty * 4 + i) sv[i][j] = -INFINITY;
        }

#pragma unroll
        for (int i = 0; i < 4; i++) {
            float rm = fmaxf(fmaxf(sv[i][0], sv[i][1]), fmaxf(sv[i][2], sv[i][3]));
#pragma unroll
            for (int m = 1; m < 16; m <<= 1) rm = fmaxf(rm, __shfl_xor_sync(0xffffffffu, rm, m));
            float mnew = fmaxf(m_i[i], rm);
            float rs = 0.f;
#pragma unroll
            for (int j = 0; j < 4; j++) {
                sv[i][j] = __expf(sv[i][j] - mnew);
                rs += sv[i][j];
            }
#pragma unroll
            for (int m = 1; m < 16; m <<= 1) rs += __shfl_xor_sync(0xffffffffu, rs, m);
            float alpha = __expf(m_i[i] - mnew);
            l_i[i] = l_i[i] * alpha + rs;
            m_i[i] = mnew;
#pragma unroll
            for (int j = 0; j < 8; j++) acc[i][j] *= alpha;
            *(float4*)&Ps[(ty * 4 + i) * LDP + tx * 4] =
                make_float4(sv[i][0], sv[i][1], sv[i][2], sv[i][3]);
        }
        __syncthreads();

        for (int k = 0; k < BN; k += 4) {
            float4 p4[4];
#pragma unroll
            for (int i = 0; i < 4; i++) p4[i] = *(const float4*)&Ps[(ty * 4 + i) * LDP + k];
#pragma unroll
            for (int kk = 0; kk < 4; kk++) {
                float4 v0 = *(const float4*)&Vs[(k + kk) * LDQ + tx * 8];
                float4 v1 = *(const float4*)&Vs[(k + kk) * LDQ + tx * 8 + 4];
#pragma unroll
                for (int i = 0; i < 4; i++) {
                    float p = ((const float*)&p4[i])[kk];
                    acc[i][0] += p * v0.x; acc[i][1] += p * v0.y;
                    acc[i][2] += p * v0.z; acc[i][3] += p * v0.w;
                    acc[i][4] += p * v1.x; acc[i][5] += p * v1.y;
                    acc[i][6] += p * v1.z; acc[i][7] += p * v1.w;
                }
            }
        }
    }

#pragma unroll
    for (int i = 0; i < 4; i++) {
        float invl = 1.0f / l_i[i];
        size_t base = (size_t)(qb * BM + ty * 4 + i) * H_DIM + h * HDIM + tx * 8;
#pragma unroll
        for (int j = 0; j < 8; j++) {
            bf16 hh, ll;
            split_bf16(acc[i][j] * invl, hh, ll);
            oh[base + j] = hh;
            ol[base + j] = ll;
        }
    }
}

// ---------------- SiLU(gate)*up -> split bf16 ----------------
__global__ void silu_mul_split_kernel(const float* __restrict__ gu,
                                      bf16* __restrict__ oh, bf16* __restrict__ ol) {
    size_t idx = (size_t)blockIdx.x * blockDim.x + threadIdx.x;
    const size_t n4 = (size_t)S_LEN * I_DIM / 4;
    if (idx >= n4) return;
    int s = (int)(idx / (I_DIM / 4));
    int c = (int)(idx % (I_DIM / 4)) * 4;
    float4 g = *(const float4*)&gu[(size_t)s * GU_N + c];
    float4 u = *(const float4*)&gu[(size_t)s * GU_N + I_DIM + c];
    float v[4];
    v[0] = g.x / (1.f + __expf(-g.x)) * u.x;
    v[1] = g.y / (1.f + __expf(-g.y)) * u.y;
    v[2] = g.z / (1.f + __expf(-g.z)) * u.z;
    v[3] = g.w / (1.f + __expf(-g.w)) * u.w;
    size_t o = (size_t)s * I_DIM + c;
#pragma unroll
    for (int j = 0; j < 4; j++) {
        bf16 h, l;
        split_bf16(v[j], h, l);
        oh[o + j] = h;
        ol[o + j] = l;
    }
}

// ---------------- host launcher ----------------
extern "C" void kernel_launch(void* const* d_in, const int* in_sizes, int n_in,
                              void* d_out, int out_size) {
    (void)in_sizes; (void)n_in; (void)out_size;
    const float* hidden = (const float*)d_in[1];
    const float* w_qkv  = (const float*)d_in[2];
    const float* w_o    = (const float*)d_in[3];
    const float* w_gu   = (const float*)d_in[4];
    const float* w_down = (const float*)d_in[5];
    const float* ln1    = (const float*)d_in[6];
    const float* ln2    = (const float*)d_in[7];

    float* out = (float*)d_out;
    float* residual = out + (size_t)S_LEN * H_DIM;

    float *qkv, *gu;
    bf16 *xn_h, *xn_l, *at_h, *at_l, *x2_h, *x2_l, *h_h, *h_l;
    bf16 *wq_h, *wq_l, *wo_h, *wo_l, *wg_h, *wg_l, *wd_h, *wd_l;
    cudaGetSymbolAddress((void**)&qkv, g_qkv);
    cudaGetSymbolAddress((void**)&gu, g_gu);
    cudaGetSymbolAddress((void**)&xn_h, g_xn_h);  cudaGetSymbolAddress((void**)&xn_l, g_xn_l);
    cudaGetSymbolAddress((void**)&at_h, g_at_h);  cudaGetSymbolAddress((void**)&at_l, g_at_l);
    cudaGetSymbolAddress((void**)&x2_h, g_x2_h);  cudaGetSymbolAddress((void**)&x2_l, g_x2_l);
    cudaGetSymbolAddress((void**)&h_h, g_h_h);    cudaGetSymbolAddress((void**)&h_l, g_h_l);
    cudaGetSymbolAddress((void**)&wq_h, g_wqkv_h); cudaGetSymbolAddress((void**)&wq_l, g_wqkv_l);
    cudaGetSymbolAddress((void**)&wo_h, g_wo_h);   cudaGetSymbolAddress((void**)&wo_l, g_wo_l);
    cudaGetSymbolAddress((void**)&wg_h, g_wgu_h);  cudaGetSymbolAddress((void**)&wg_l, g_wgu_l);
    cudaGetSymbolAddress((void**)&wd_h, g_wdn_h);  cudaGetSymbolAddress((void**)&wd_l, g_wdn_l);

    cudaFuncSetAttribute(mma_gemm<false>, cudaFuncAttributeMaxDynamicSharedMemorySize, GEMM_SMEM);
    cudaFuncSetAttribute(mma_gemm<true>,  cudaFuncAttributeMaxDynamicSharedMemorySize, GEMM_SMEM);
    cudaFuncSetAttribute(attn_kernel,     cudaFuncAttributeMaxDynamicSharedMemorySize, ATTN_SMEM);

    // weight prep (transpose + hi/lo split)
    wsplit_t_kernel<<<dim3(QKV_N / 32, H_DIM / 32), 256>>>(w_qkv, wq_h, wq_l, H_DIM, QKV_N);
    wsplit_t_kernel<<<dim3(H_DIM / 32, H_DIM / 32), 256>>>(w_o, wo_h, wo_l, H_DIM, H_DIM);
    wsplit_t_kernel<<<dim3(GU_N / 32, H_DIM / 32), 256>>>(w_gu, wg_h, wg_l, H_DIM, GU_N);
    wsplit_t_kernel<<<dim3(H_DIM / 32, I_DIM / 32), 256>>>(w_down, wd_h, wd_l, I_DIM, H_DIM);

    // 1) rmsnorm1 -> split
    rmsnorm_split_kernel<<<S_LEN, 256>>>(hidden, ln1, xn_h, xn_l);
    // 2) qkv = xn @ w_qkv
    mma_gemm<false><<<dim3(S_LEN / 128, QKV_N / 128), 256, GEMM_SMEM>>>(
        xn_h, xn_l, wq_h, wq_l, nullptr, qkv, QKV_N, H_DIM);
    // 3) rope
    rope_kernel<<<dim3(S_LEN, NQH + NKVH), 64>>>(qkv);
    // 4) attention -> split bf16
    attn_kernel<<<dim3(S_LEN / BM, NQH), 256, ATTN_SMEM>>>(qkv, at_h, at_l);
    // 5) residual = attn @ w_o + hidden
    mma_gemm<true><<<dim3(S_LEN / 128, H_DIM / 128), 256, GEMM_SMEM>>>(
        at_h, at_l, wo_h, wo_l, hidden, residual, H_DIM, H_DIM);
    // 6) rmsnorm2 -> split
    rmsnorm_split_kernel<<<S_LEN, 256>>>(residual, ln2, x2_h, x2_l);
    // 7) gate_up = x2 @ w_gate_up
    mma_gemm<false><<<dim3(S_LEN / 128, GU_N / 128), 256, GEMM_SMEM>>>(
        x2_h, x2_l, wg_h, wg_l, nullptr, gu, GU_N, H_DIM);
    // 8) silu * up -> split
    {
        size_t n4 = (size_t)S_LEN * I_DIM / 4;
        silu_mul_split_kernel<<<(int)((n4 + 255) / 256), 256>>>(gu, h_h, h_l);
    }
    // 9) out = h @ w_down
    mma_gemm<false><<<dim3(S_LEN / 128, H_DIM / 128), 256, GEMM_SMEM>>>(
        h_h, h_l, wd_h, wd_l, nullptr, out, H_DIM, I_DIM);
}